// round 1
// baseline (speedup 1.0000x reference)
#include <cuda_runtime.h>
#include <math.h>

// Problem constants
#define NROWS   9216      // B*R = 256*36
#define IMG     2048
#define TAG     768
#define K1      2816      // IMG+TAG
#define K2RAW   3016      // IMG+POS_EMBED+TAG
#define K2      3072      // padded to /16
#define N1      200       // POS_EMBED
#define N2      1024      // EMBED_SIZE
#define BOXL    15
#define PEMB    200

// Scratch (static device globals: allowed; no runtime allocation)
__device__ float g_X[(long)NROWS * K2];     // packed input rows [img|tag|box_feat|pad0]
__device__ float g_region[(long)NROWS * N1];
__device__ float g_W2[(long)N2 * K2];       // fc_W with columns permuted to X layout

// ---------------------------------------------------------------------------
// Pack X: images -> cols [0,2048), tag -> [2048,2816), pad -> [3016,3072)=0.
// box_feat region [2816,3016) is filled later by attn_kernel.
// One float4 slot per thread; 768 slots per row.
__global__ void packX_kernel(const float* __restrict__ images,
                             const float* __restrict__ tag) {
    int i = blockIdx.x * blockDim.x + threadIdx.x;
    if (i >= NROWS * 768) return;
    int row = i / 768;
    int c4  = i - row * 768;
    float4 v;
    if (c4 < 512) {
        v = reinterpret_cast<const float4*>(images)[(long)row * 512 + c4];
    } else if (c4 < 704) {
        v = reinterpret_cast<const float4*>(tag)[(long)row * 192 + (c4 - 512)];
    } else if (c4 < 754) {
        return;                       // box_feat region, written by attn kernel
    } else {
        v = make_float4(0.f, 0.f, 0.f, 0.f);
    }
    reinterpret_cast<float4*>(g_X + (long)row * K2)[c4] = v;
}

// Permute fc_W [1024, 3016] (img|box|tag) -> g_W2 [1024, 3072] (img|tag|box|0)
__global__ void permW_kernel(const float* __restrict__ fcW) {
    int i = blockIdx.x * blockDim.x + threadIdx.x;
    if (i >= N2 * K2) return;
    int n = i / K2;
    int k = i - n * K2;
    float v;
    if (k < 2048)       v = fcW[(long)n * K2RAW + k];          // images
    else if (k < 2816)  v = fcW[(long)n * K2RAW + k + 200];    // tag (src 2248..3015)
    else if (k < 3016)  v = fcW[(long)n * K2RAW + k - 768];    // box_feat (src 2048..2247)
    else                v = 0.f;                                // pad
    g_W2[i] = v;
}

// ---------------------------------------------------------------------------
// SGEMM: C[M,N] = A[M,K(lda)] * Bw[N,K]^T (+bias). BM=128 BN=64 BK=16,
// 256 threads, 8x4 micro-tile per thread. M % 128 == 0, K % 16 == 0 assumed;
// N bounds are predicated.
__global__ void __launch_bounds__(256)
sgemm_kernel(const float* __restrict__ A, int lda,
             const float* __restrict__ Bw, int K,
             const float* __restrict__ bias,
             float* __restrict__ C, int N, int ldc) {
    const int BM = 128, BN = 64, BK = 16;
    __shared__ float As[BK][BM];
    __shared__ float Bs[BK][BN];

    int tid = threadIdx.x;
    int tx = tid & 15;        // 0..15 -> N
    int ty = tid >> 4;        // 0..15 -> M
    int m0 = blockIdx.y * BM;
    int n0 = blockIdx.x * BN;

    float acc[8][4];
#pragma unroll
    for (int i = 0; i < 8; i++)
#pragma unroll
        for (int j = 0; j < 4; j++) acc[i][j] = 0.f;

    for (int k0 = 0; k0 < K; k0 += BK) {
        // Load A tile: 512 float4 slots, 2 per thread
#pragma unroll
        for (int t = 0; t < 2; t++) {
            int s = tid * 2 + t;
            int m = s >> 2;
            int kq = s & 3;
            float4 v = *reinterpret_cast<const float4*>(
                A + (long)(m0 + m) * lda + k0 + kq * 4);
            As[kq * 4 + 0][m] = v.x;
            As[kq * 4 + 1][m] = v.y;
            As[kq * 4 + 2][m] = v.z;
            As[kq * 4 + 3][m] = v.w;
        }
        // Load B tile: 256 float4 slots, 1 per thread
        {
            int n = tid >> 2;
            int kq = tid & 3;
            float4 v = make_float4(0.f, 0.f, 0.f, 0.f);
            if (n0 + n < N)
                v = *reinterpret_cast<const float4*>(
                    Bw + (long)(n0 + n) * K + k0 + kq * 4);
            Bs[kq * 4 + 0][n] = v.x;
            Bs[kq * 4 + 1][n] = v.y;
            Bs[kq * 4 + 2][n] = v.z;
            Bs[kq * 4 + 3][n] = v.w;
        }
        __syncthreads();

#pragma unroll
        for (int kk = 0; kk < BK; kk++) {
            float a[8], b[4];
            *reinterpret_cast<float4*>(&a[0]) =
                *reinterpret_cast<const float4*>(&As[kk][ty * 8]);
            *reinterpret_cast<float4*>(&a[4]) =
                *reinterpret_cast<const float4*>(&As[kk][ty * 8 + 4]);
            *reinterpret_cast<float4*>(&b[0]) =
                *reinterpret_cast<const float4*>(&Bs[kk][tx * 4]);
#pragma unroll
            for (int i = 0; i < 8; i++)
#pragma unroll
                for (int j = 0; j < 4; j++)
                    acc[i][j] += a[i] * b[j];
        }
        __syncthreads();
    }

#pragma unroll
    for (int i = 0; i < 8; i++) {
        int m = m0 + ty * 8 + i;
#pragma unroll
        for (int j = 0; j < 4; j++) {
            int n = n0 + tx * 4 + j;
            if (n < N) {
                float v = acc[i][j];
                if (bias) v += bias[n];
                C[(long)m * ldc + n] = v;
            }
        }
    }
}

// ---------------------------------------------------------------------------
// Attention: one warp per row. Computes scores = region . pos_emb[idx_k],
// softmax(tanh) * w, renorm, box_feat -> g_X[:, 2816:3016].
__global__ void attn_kernel(const float* __restrict__ boxes,
                            const float* __restrict__ pos_emb) {
    int row  = blockIdx.x * 8 + (threadIdx.x >> 5);
    int lane = threadIdx.x & 31;
    if (row >= NROWS) return;

    const float* region = g_region + (long)row * N1;
    float reg[7];
#pragma unroll
    for (int i = 0; i < 7; i++) {
        int e = lane + 32 * i;
        reg[i] = (e < PEMB) ? region[e] : 0.f;
    }

    const float* brow = boxes + (long)row * (2 * BOXL);
    int   idx[BOXL];
    float w[BOXL], sc[BOXL];
#pragma unroll
    for (int k = 0; k < BOXL; k++) {
        idx[k] = (int)brow[k];
        w[k]   = brow[BOXL + k];
    }

#pragma unroll
    for (int k = 0; k < BOXL; k++) {
        const float* pe = pos_emb + (long)idx[k] * PEMB;
        float p = 0.f;
#pragma unroll
        for (int i = 0; i < 7; i++) {
            int e = lane + 32 * i;
            if (e < PEMB) p += reg[i] * pe[e];
        }
#pragma unroll
        for (int o = 16; o > 0; o >>= 1)
            p += __shfl_xor_sync(0xffffffffu, p, o);
        sc[k] = tanhf(p);
    }

    float mx = -1e30f;
#pragma unroll
    for (int k = 0; k < BOXL; k++) mx = fmaxf(mx, sc[k]);
    float ssum = 0.f;
#pragma unroll
    for (int k = 0; k < BOXL; k++) { sc[k] = expf(sc[k] - mx); ssum += sc[k]; }
    float tot = 0.f;
#pragma unroll
    for (int k = 0; k < BOXL; k++) { sc[k] = sc[k] / ssum * w[k]; tot += sc[k]; }
    float inv = 1.f / (tot + 1e-6f);

#pragma unroll
    for (int i = 0; i < 7; i++) {
        int e = lane + 32 * i;
        if (e < PEMB) {
            float f = 0.f;
#pragma unroll
            for (int k = 0; k < BOXL; k++)
                f += sc[k] * pos_emb[(long)idx[k] * PEMB + e];
            g_X[(long)row * K2 + K1 + e] = f * inv;
        }
    }
}

// ---------------------------------------------------------------------------
// L2 normalize rows of out [NROWS, 1024] in place. One warp per row.
__global__ void norm_kernel(float* __restrict__ out) {
    int row  = blockIdx.x * 8 + (threadIdx.x >> 5);
    int lane = threadIdx.x & 31;
    if (row >= NROWS) return;

    float4* p = reinterpret_cast<float4*>(out + (long)row * N2);
    float4 v[8];
    float s = 0.f;
#pragma unroll
    for (int i = 0; i < 8; i++) {
        v[i] = p[lane + 32 * i];
        s += v[i].x * v[i].x + v[i].y * v[i].y + v[i].z * v[i].z + v[i].w * v[i].w;
    }
#pragma unroll
    for (int o = 16; o > 0; o >>= 1)
        s += __shfl_xor_sync(0xffffffffu, s, o);
    float scale = 1.f / (sqrtf(s) + 1e-8f);
#pragma unroll
    for (int i = 0; i < 8; i++) {
        v[i].x *= scale; v[i].y *= scale; v[i].z *= scale; v[i].w *= scale;
        p[lane + 32 * i] = v[i];
    }
}

// ---------------------------------------------------------------------------
extern "C" void kernel_launch(void* const* d_in, const int* in_sizes, int n_in,
                              void* d_out, int out_size) {
    const float* images   = (const float*)d_in[0];
    const float* tag      = (const float*)d_in[1];
    const float* boxes    = (const float*)d_in[2];
    const float* pos_emb  = (const float*)d_in[3];
    const float* attn_W   = (const float*)d_in[4];
    const float* fc_W     = (const float*)d_in[5];
    const float* fc_b     = (const float*)d_in[6];
    float* out = (float*)d_out;

    void *xp, *rp, *wp;
    cudaGetSymbolAddress(&xp, g_X);
    cudaGetSymbolAddress(&rp, g_region);
    cudaGetSymbolAddress(&wp, g_W2);
    float* X  = (float*)xp;
    float* Rg = (float*)rp;
    float* W2 = (float*)wp;

    // 1. Pack X (images|tag|..|pad) and permute fc_W
    packX_kernel<<<(NROWS * 768 + 255) / 256, 256>>>(images, tag);
    permW_kernel<<<(N2 * K2 + 255) / 256, 256>>>(fc_W);

    // 2. GEMM1: region = X[:, :2816] @ attn_W^T   (M=9216, N=200, K=2816)
    {
        dim3 grid((N1 + 63) / 64, NROWS / 128);
        sgemm_kernel<<<grid, 256>>>(X, K2, attn_W, K1, nullptr, Rg, N1, N1);
    }

    // 3. Attention -> box_feat into X[:, 2816:3016]
    attn_kernel<<<NROWS / 8, 256>>>(boxes, pos_emb);

    // 4. GEMM2: out = X @ W2^T + fc_b   (M=9216, N=1024, K=3072 padded)
    {
        dim3 grid(N2 / 64, NROWS / 128);
        sgemm_kernel<<<grid, 256>>>(X, K2, W2, K2, fc_b, out, N2, N2);
    }

    // 5. L2 normalize rows in place
    norm_kernel<<<NROWS / 8, 256>>>(out);
}

// round 3
// speedup vs baseline: 2.4624x; 2.4624x over previous
#include <cuda_runtime.h>
#include <cuda_bf16.h>
#include <math.h>
#include <stdint.h>

// ---------------------------------------------------------------- constants
#define NROWS   9216      // B*R
#define K1      2816      // IMG+TAG
#define K2      3072      // padded (3016 -> 3072)
#define K2RAW   3016
#define N1      200       // POS_EMBED
#define N1P     256       // padded
#define N2      1024
#define BOXL    15
#define PEMB    200

// GEMM tiling
#define BM      256
#define BN      128
#define BK      32
#define STG     3
#define ROWB    80                  // padded row stride bytes (32 bf16 -> 80B)
#define T_AH    0
#define T_AL    (BM*ROWB)           // 20480
#define T_BH    (2*BM*ROWB)         // 40960
#define T_BL    (2*BM*ROWB + BN*ROWB)  // 51200
#define STAGE_B (2*BM*ROWB + 2*BN*ROWB) // 61440
#define SMEM_SZ (STG*STAGE_B)       // 184320

// ---------------------------------------------------------------- scratch
__device__ __nv_bfloat16 g_Xh[(long)NROWS * K2];
__device__ __nv_bfloat16 g_Xl[(long)NROWS * K2];
__device__ __nv_bfloat16 g_W2h[(long)N2 * K2];
__device__ __nv_bfloat16 g_W2l[(long)N2 * K2];
__device__ __nv_bfloat16 g_W1h[(long)N1P * K1];
__device__ __nv_bfloat16 g_W1l[(long)N1P * K1];
__device__ float g_region[(long)NROWS * N1];

// ---------------------------------------------------------------- utils
__device__ __forceinline__ uint32_t smem_u32(const void* p) {
    uint32_t a;
    asm("{ .reg .u64 t; cvta.to.shared.u64 t, %1; cvt.u32.u64 %0, t; }"
        : "=r"(a) : "l"(p));
    return a;
}
__device__ __forceinline__ void cp16(uint32_t dst, const void* src) {
    asm volatile("cp.async.cg.shared.global [%0], [%1], 16;" :: "r"(dst), "l"(src));
}
__device__ __forceinline__ void cp_commit() {
    asm volatile("cp.async.commit_group;" ::: "memory");
}
__device__ __forceinline__ void cp_wait1() {
    asm volatile("cp.async.wait_group 1;" ::: "memory");
}
__device__ __forceinline__ void ldsm4(uint32_t* r, uint32_t addr) {
    asm volatile("ldmatrix.sync.aligned.m8n8.x4.shared.b16 {%0,%1,%2,%3}, [%4];"
                 : "=r"(r[0]), "=r"(r[1]), "=r"(r[2]), "=r"(r[3]) : "r"(addr));
}
__device__ __forceinline__ void mma16816(float* d, const uint32_t* a,
                                         uint32_t b0, uint32_t b1) {
    asm volatile(
        "mma.sync.aligned.m16n8k16.row.col.f32.bf16.bf16.f32 "
        "{%0,%1,%2,%3}, {%4,%5,%6,%7}, {%8,%9}, {%0,%1,%2,%3};"
        : "+f"(d[0]), "+f"(d[1]), "+f"(d[2]), "+f"(d[3])
        : "r"(a[0]), "r"(a[1]), "r"(a[2]), "r"(a[3]), "r"(b0), "r"(b1));
}
__device__ __forceinline__ void split2(float v, __nv_bfloat16& h, __nv_bfloat16& l) {
    h = __float2bfloat16(v);
    l = __float2bfloat16(v - __bfloat162float(h));
}

// ---------------------------------------------------------------- conversions
__global__ void convX_kernel(const float* __restrict__ images,
                             const float* __restrict__ tag) {
    int i = blockIdx.x * blockDim.x + threadIdx.x;
    if (i >= NROWS * 768) return;
    int row = i / 768;
    int c4  = i - row * 768;
    float4 v;
    if (c4 < 512)      v = reinterpret_cast<const float4*>(images)[(long)row * 512 + c4];
    else if (c4 < 704) v = reinterpret_cast<const float4*>(tag)[(long)row * 192 + (c4 - 512)];
    else if (c4 < 754) return;   // box_feat region: written by attn kernel
    else               v = make_float4(0.f, 0.f, 0.f, 0.f);
    long base = (long)row * K2 + c4 * 4;
    __nv_bfloat16 h[4], l[4];
    split2(v.x, h[0], l[0]); split2(v.y, h[1], l[1]);
    split2(v.z, h[2], l[2]); split2(v.w, h[3], l[3]);
    *reinterpret_cast<uint2*>(g_Xh + base) = *reinterpret_cast<uint2*>(h);
    *reinterpret_cast<uint2*>(g_Xl + base) = *reinterpret_cast<uint2*>(l);
}

__global__ void convW2_kernel(const float* __restrict__ fcW) {
    int i = blockIdx.x * blockDim.x + threadIdx.x;
    if (i >= N2 * K2) return;
    int n = i / K2;
    int k = i - n * K2;
    float v;
    if (k < 2048)      v = fcW[(long)n * K2RAW + k];
    else if (k < 2816) v = fcW[(long)n * K2RAW + k + 200];
    else if (k < 3016) v = fcW[(long)n * K2RAW + k - 768];
    else               v = 0.f;
    __nv_bfloat16 h, l; split2(v, h, l);
    g_W2h[i] = h; g_W2l[i] = l;
}

__global__ void convW1_kernel(const float* __restrict__ aW) {
    int i = blockIdx.x * blockDim.x + threadIdx.x;
    if (i >= N1P * K1) return;
    int n = i / K1;
    int k = i - n * K1;
    float v = (n < N1) ? aW[(long)n * K1 + k] : 0.f;
    __nv_bfloat16 h, l; split2(v, h, l);
    g_W1h[i] = h; g_W1l[i] = l;
}

// ---------------------------------------------------------------- HMMA GEMM
// C[M,N] = A[M,K]*B[N,K]^T (+bias), A=(Ah,Al), B=(Bh,Bl) bf16 split.
// acc += Ah*Bh + Ah*Bl + Al*Bh. BM=256 BN=128 BK=32, 512 threads,
// warp grid 8(M) x 2(N), warp tile 32x64, mma m16n8k16.
__global__ void __launch_bounds__(512, 1)
hmma_gemm(const __nv_bfloat16* __restrict__ Ah, const __nv_bfloat16* __restrict__ Al, int lda,
          const __nv_bfloat16* __restrict__ Bh, const __nv_bfloat16* __restrict__ Bl, int ldb,
          int K, const float* __restrict__ bias,
          float* __restrict__ C, int N, int ldc) {
    extern __shared__ char smem[];
    const uint32_t sb = smem_u32(smem);
    const int tid  = threadIdx.x;
    const int lane = tid & 31;
    const int wid  = tid >> 5;
    const int wm   = (wid & 7) * 32;
    const int wn   = (wid >> 3) * 64;
    const long m0  = (long)blockIdx.y * BM;
    const long n0  = (long)blockIdx.x * BN;

    float acc[2][8][4];
#pragma unroll
    for (int i = 0; i < 2; i++)
#pragma unroll
        for (int j = 0; j < 8; j++)
#pragma unroll
            for (int c = 0; c < 4; c++) acc[i][j][c] = 0.f;

    // ldmatrix per-thread offsets (within stage)
    // A x4: lanes 0-15 -> rows m0..15 (khalf 0), lanes 16-31 -> rows (khalf 1)
    uint32_t a_off[2];
#pragma unroll
    for (int mt = 0; mt < 2; mt++)
        a_off[mt] = (uint32_t)(wm + mt * 16 + (lane & 15)) * ROWB + (lane >> 4) * 16;
    // B x4 (two n8 tiles): lanes0-7 n0-7@k0, 8-15 n0-7@k8, 16-23 n8-15@k0, 24-31 n8-15@k8
    uint32_t b_off[4];
#pragma unroll
    for (int np = 0; np < 4; np++)
        b_off[np] = T_BH
                  + (uint32_t)(wn + np * 16 + ((lane & 7) | ((lane >> 4) << 3))) * ROWB
                  + ((lane >> 3) & 1) * 16;

    // loader: 6 cp16 per thread per stage
    const int arow = tid >> 2, aks = tid & 3;
    const uint32_t asw = (uint32_t)arow * ROWB + aks * 16;
    const uint32_t asw2 = (uint32_t)(arow + 128) * ROWB + aks * 16;

    const int S = K / BK;
    int ls = 0;            // stage about to be loaded
    long lk = 0;           // its k offset (elements)

#pragma unroll 1
    for (int p = 0; p < STG - 1; p++) {
        uint32_t st = sb + ls * STAGE_B;
        const __nv_bfloat16* pa = Ah + (m0 + arow) * lda + lk + aks * 8;
        const __nv_bfloat16* pl = Al + (m0 + arow) * lda + lk + aks * 8;
        cp16(st + T_AH + asw, pa);
        cp16(st + T_AL + asw, pl);
        cp16(st + T_AH + asw2, pa + (long)128 * lda);
        cp16(st + T_AL + asw2, pl + (long)128 * lda);
        cp16(st + asw + T_BH, Bh + (n0 + arow) * ldb + lk + aks * 8);
        cp16(st + asw + T_BL, Bl + (n0 + arow) * ldb + lk + aks * 8);
        cp_commit();
        ls++; if (ls == STG) ls = 0;
        lk += BK;
    }

    int cs = 0;            // stage being computed
#pragma unroll 1
    for (int s = 0; s < S; s++) {
        if (s + STG - 1 < S) {
            uint32_t st = sb + ls * STAGE_B;
            const __nv_bfloat16* pa = Ah + (m0 + arow) * lda + lk + aks * 8;
            const __nv_bfloat16* pl = Al + (m0 + arow) * lda + lk + aks * 8;
            cp16(st + T_AH + asw, pa);
            cp16(st + T_AL + asw, pl);
            cp16(st + T_AH + asw2, pa + (long)128 * lda);
            cp16(st + T_AL + asw2, pl + (long)128 * lda);
            cp16(st + asw + T_BH, Bh + (n0 + arow) * ldb + lk + aks * 8);
            cp16(st + asw + T_BL, Bl + (n0 + arow) * ldb + lk + aks * 8);
            ls++; if (ls == STG) ls = 0;
            lk += BK;
        }
        cp_commit();
        cp_wait1();
        __syncthreads();

        uint32_t st = sb + cs * STAGE_B;
#pragma unroll
        for (int kk = 0; kk < 2; kk++) {
            uint32_t ah[2][4], al[2][4];
#pragma unroll
            for (int mt = 0; mt < 2; mt++) {
                ldsm4(ah[mt], st + a_off[mt] + kk * 32);
                ldsm4(al[mt], st + T_AL + a_off[mt] + kk * 32);
            }
#pragma unroll
            for (int np = 0; np < 4; np++) {
                uint32_t bh[4], bl[4];
                ldsm4(bh, st + b_off[np] + kk * 32);
                ldsm4(bl, st + (T_BL - T_BH) + b_off[np] + kk * 32);
#pragma unroll
                for (int j = 0; j < 2; j++) {
                    int nt = np * 2 + j;
#pragma unroll
                    for (int mt = 0; mt < 2; mt++) {
                        mma16816(acc[mt][nt], ah[mt], bh[2 * j], bh[2 * j + 1]);
                        mma16816(acc[mt][nt], ah[mt], bl[2 * j], bl[2 * j + 1]);
                        mma16816(acc[mt][nt], al[mt], bh[2 * j], bh[2 * j + 1]);
                    }
                }
            }
        }
        __syncthreads();
        cs++; if (cs == STG) cs = 0;
    }

    // epilogue
    const int gr = lane >> 2;
    const int gc = (lane & 3) * 2;
#pragma unroll
    for (int mt = 0; mt < 2; mt++) {
#pragma unroll
        for (int nt = 0; nt < 8; nt++) {
            int n = (int)n0 + wn + nt * 8 + gc;
            if (n < N) {
                long m = m0 + wm + mt * 16 + gr;
                float b0 = bias ? bias[n] : 0.f;
                float b1 = bias ? bias[n + 1] : 0.f;
                float2 v0 = make_float2(acc[mt][nt][0] + b0, acc[mt][nt][1] + b1);
                float2 v1 = make_float2(acc[mt][nt][2] + b0, acc[mt][nt][3] + b1);
                *reinterpret_cast<float2*>(C + m * ldc + n) = v0;
                *reinterpret_cast<float2*>(C + (m + 8) * ldc + n) = v1;
            }
        }
    }
}

// ---------------------------------------------------------------- attention
__global__ void attn_kernel(const float* __restrict__ boxes,
                            const float* __restrict__ pos_emb) {
    int row  = blockIdx.x * 8 + (threadIdx.x >> 5);
    int lane = threadIdx.x & 31;
    if (row >= NROWS) return;

    const float* region = g_region + (long)row * N1;
    float reg[7];
#pragma unroll
    for (int i = 0; i < 7; i++) {
        int e = lane + 32 * i;
        reg[i] = (e < PEMB) ? region[e] : 0.f;
    }

    const float* brow = boxes + (long)row * (2 * BOXL);
    int   idx[BOXL];
    float w[BOXL], sc[BOXL];
#pragma unroll
    for (int k = 0; k < BOXL; k++) {
        idx[k] = (int)brow[k];
        w[k]   = brow[BOXL + k];
    }

#pragma unroll
    for (int k = 0; k < BOXL; k++) {
        const float* pe = pos_emb + (long)idx[k] * PEMB;
        float p = 0.f;
#pragma unroll
        for (int i = 0; i < 7; i++) {
            int e = lane + 32 * i;
            if (e < PEMB) p += reg[i] * pe[e];
        }
#pragma unroll
        for (int o = 16; o > 0; o >>= 1)
            p += __shfl_xor_sync(0xffffffffu, p, o);
        sc[k] = tanhf(p);
    }

    float mx = -1e30f;
#pragma unroll
    for (int k = 0; k < BOXL; k++) mx = fmaxf(mx, sc[k]);
    float ssum = 0.f;
#pragma unroll
    for (int k = 0; k < BOXL; k++) { sc[k] = expf(sc[k] - mx); ssum += sc[k]; }
    float tot = 0.f;
#pragma unroll
    for (int k = 0; k < BOXL; k++) { sc[k] = sc[k] / ssum * w[k]; tot += sc[k]; }
    float inv = 1.f / (tot + 1e-6f);

#pragma unroll
    for (int i = 0; i < 7; i++) {
        int e = lane + 32 * i;
        if (e < PEMB) {
            float f = 0.f;
#pragma unroll
            for (int k = 0; k < BOXL; k++)
                f += sc[k] * pos_emb[(long)idx[k] * PEMB + e];
            f *= inv;
            __nv_bfloat16 h, l; split2(f, h, l);
            g_Xh[(long)row * K2 + K1 + e] = h;
            g_Xl[(long)row * K2 + K1 + e] = l;
        }
    }
}

// ---------------------------------------------------------------- L2 norm
__global__ void norm_kernel(float* __restrict__ out) {
    int row  = blockIdx.x * 8 + (threadIdx.x >> 5);
    int lane = threadIdx.x & 31;
    if (row >= NROWS) return;

    float4* p = reinterpret_cast<float4*>(out + (long)row * N2);
    float4 v[8];
    float s = 0.f;
#pragma unroll
    for (int i = 0; i < 8; i++) {
        v[i] = p[lane + 32 * i];
        s += v[i].x * v[i].x + v[i].y * v[i].y + v[i].z * v[i].z + v[i].w * v[i].w;
    }
#pragma unroll
    for (int o = 16; o > 0; o >>= 1)
        s += __shfl_xor_sync(0xffffffffu, s, o);
    float scale = 1.f / (sqrtf(s) + 1e-8f);
#pragma unroll
    for (int i = 0; i < 8; i++) {
        v[i].x *= scale; v[i].y *= scale; v[i].z *= scale; v[i].w *= scale;
        p[lane + 32 * i] = v[i];
    }
}

// ---------------------------------------------------------------- launch
extern "C" void kernel_launch(void* const* d_in, const int* in_sizes, int n_in,
                              void* d_out, int out_size) {
    const float* images  = (const float*)d_in[0];
    const float* tag     = (const float*)d_in[1];
    const float* boxes   = (const float*)d_in[2];
    const float* pos_emb = (const float*)d_in[3];
    const float* attn_W  = (const float*)d_in[4];
    const float* fc_W    = (const float*)d_in[5];
    const float* fc_b    = (const float*)d_in[6];
    float* out = (float*)d_out;

    cudaFuncSetAttribute(hmma_gemm, cudaFuncAttributeMaxDynamicSharedMemorySize,
                         SMEM_SZ);

    void *xh, *xl, *w2h, *w2l, *w1h, *w1l, *rg;
    cudaGetSymbolAddress(&xh, g_Xh);   cudaGetSymbolAddress(&xl, g_Xl);
    cudaGetSymbolAddress(&w2h, g_W2h); cudaGetSymbolAddress(&w2l, g_W2l);
    cudaGetSymbolAddress(&w1h, g_W1h); cudaGetSymbolAddress(&w1l, g_W1l);
    cudaGetSymbolAddress(&rg, g_region);

    // 1. conversions
    convX_kernel<<<(NROWS * 768 + 255) / 256, 256>>>(images, tag);
    convW2_kernel<<<(N2 * K2 + 255) / 256, 256>>>(fc_W);
    convW1_kernel<<<(N1P * K1 + 255) / 256, 256>>>(attn_W);

    // 2. GEMM1: region = X[:, :2816] @ attn_W^T  (N padded 256, store N=200)
    {
        dim3 grid(N1P / BN, NROWS / BM);
        hmma_gemm<<<grid, 512, SMEM_SZ>>>(
            (const __nv_bfloat16*)xh, (const __nv_bfloat16*)xl, K2,
            (const __nv_bfloat16*)w1h, (const __nv_bfloat16*)w1l, K1,
            K1, nullptr, (float*)rg, N1, N1);
    }

    // 3. attention -> box_feat (bf16 split) into X[:, 2816:3016]
    attn_kernel<<<NROWS / 8, 256>>>(boxes, pos_emb);

    // 4. GEMM2: out = X @ W2^T + fc_b
    {
        dim3 grid(N2 / BN, NROWS / BM);
        hmma_gemm<<<grid, 512, SMEM_SZ>>>(
            (const __nv_bfloat16*)xh, (const __nv_bfloat16*)xl, K2,
            (const __nv_bfloat16*)w2h, (const __nv_bfloat16*)w2l, K2,
            K2, fc_b, out, N2, N2);
    }

    // 5. L2 normalize
    norm_kernel<<<NROWS / 8, 256>>>(out);
}

// round 4
// speedup vs baseline: 2.8747x; 1.1675x over previous
#include <cuda_runtime.h>
#include <cuda_bf16.h>
#include <math.h>
#include <stdint.h>

// ---------------------------------------------------------------- constants
#define NROWS   9216      // B*R
#define K1      2816      // IMG+TAG
#define K2      3072      // padded (3016 -> 3072)
#define K2RAW   3016
#define N1      200       // POS_EMBED
#define N1P     256       // padded
#define N2      1024
#define BOXL    15
#define PEMB    200

#define BN      128
#define BK      32
#define ROWB    80        // padded row stride bytes (32 bf16 = 64B data + 16B pad)

// ---------------------------------------------------------------- scratch
__device__ __nv_bfloat16 g_Xh[(long)NROWS * K2];
__device__ __nv_bfloat16 g_Xl[(long)NROWS * K2];
__device__ __nv_bfloat16 g_W2h[(long)N2 * K2];
__device__ __nv_bfloat16 g_W2l[(long)N2 * K2];
__device__ __nv_bfloat16 g_W1h[(long)N1P * K1];
__device__ __nv_bfloat16 g_W1l[(long)N1P * K1];
__device__ float g_region[(long)NROWS * N1];

// ---------------------------------------------------------------- utils
__device__ __forceinline__ uint32_t smem_u32(const void* p) {
    uint32_t a;
    asm("{ .reg .u64 t; cvta.to.shared.u64 t, %1; cvt.u32.u64 %0, t; }"
        : "=r"(a) : "l"(p));
    return a;
}
__device__ __forceinline__ void cp16(uint32_t dst, const void* src) {
    asm volatile("cp.async.cg.shared.global [%0], [%1], 16;" :: "r"(dst), "l"(src));
}
__device__ __forceinline__ void cp_commit() {
    asm volatile("cp.async.commit_group;" ::: "memory");
}
template<int N>
__device__ __forceinline__ void cp_wait() {
    asm volatile("cp.async.wait_group %0;" :: "n"(N) : "memory");
}
__device__ __forceinline__ void ldsm4(uint32_t* r, uint32_t addr) {
    asm volatile("ldmatrix.sync.aligned.m8n8.x4.shared.b16 {%0,%1,%2,%3}, [%4];"
                 : "=r"(r[0]), "=r"(r[1]), "=r"(r[2]), "=r"(r[3]) : "r"(addr));
}
__device__ __forceinline__ void mma16816(float* d, const uint32_t* a,
                                         uint32_t b0, uint32_t b1) {
    asm volatile(
        "mma.sync.aligned.m16n8k16.row.col.f32.bf16.bf16.f32 "
        "{%0,%1,%2,%3}, {%4,%5,%6,%7}, {%8,%9}, {%0,%1,%2,%3};"
        : "+f"(d[0]), "+f"(d[1]), "+f"(d[2]), "+f"(d[3])
        : "r"(a[0]), "r"(a[1]), "r"(a[2]), "r"(a[3]), "r"(b0), "r"(b1));
}
__device__ __forceinline__ void split2(float v, __nv_bfloat16& h, __nv_bfloat16& l) {
    h = __float2bfloat16(v);
    l = __float2bfloat16(v - __bfloat162float(h));
}

// ---------------------------------------------------------------- conversions
__global__ void convX_kernel(const float* __restrict__ images,
                             const float* __restrict__ tag) {
    int i = blockIdx.x * blockDim.x + threadIdx.x;
    if (i >= NROWS * 768) return;
    int row = i / 768;
    int c4  = i - row * 768;
    float4 v;
    if (c4 < 512)      v = reinterpret_cast<const float4*>(images)[(long)row * 512 + c4];
    else if (c4 < 704) v = reinterpret_cast<const float4*>(tag)[(long)row * 192 + (c4 - 512)];
    else if (c4 < 754) return;   // box_feat region: written by attn kernel
    else               v = make_float4(0.f, 0.f, 0.f, 0.f);
    long base = (long)row * K2 + c4 * 4;
    __nv_bfloat16 h[4], l[4];
    split2(v.x, h[0], l[0]); split2(v.y, h[1], l[1]);
    split2(v.z, h[2], l[2]); split2(v.w, h[3], l[3]);
    *reinterpret_cast<uint2*>(g_Xh + base) = *reinterpret_cast<uint2*>(h);
    *reinterpret_cast<uint2*>(g_Xl + base) = *reinterpret_cast<uint2*>(l);
}

__global__ void convW2_kernel(const float* __restrict__ fcW) {
    int i = blockIdx.x * blockDim.x + threadIdx.x;
    if (i >= N2 * K2) return;
    int n = i / K2;
    int k = i - n * K2;
    float v;
    if (k < 2048)      v = fcW[(long)n * K2RAW + k];
    else if (k < 2816) v = fcW[(long)n * K2RAW + k + 200];
    else if (k < 3016) v = fcW[(long)n * K2RAW + k - 768];
    else               v = 0.f;
    __nv_bfloat16 h, l; split2(v, h, l);
    g_W2h[i] = h; g_W2l[i] = l;
}

__global__ void convW1_kernel(const float* __restrict__ aW) {
    int i = blockIdx.x * blockDim.x + threadIdx.x;
    if (i >= N1P * K1) return;
    int n = i / K1;
    int k = i - n * K1;
    float v = (n < N1) ? aW[(long)n * K1 + k] : 0.f;
    __nv_bfloat16 h, l; split2(v, h, l);
    g_W1h[i] = h; g_W1l[i] = l;
}

// ---------------------------------------------------------------- HMMA GEMM
// C[M,N] = A[M,K]*B[N,K]^T (+bias), split-x3: acc += Ah*Bh + Ah*Bl + Al*Bh.
// Template: TBM rows per CTA, MW x NW warp grid (512 threads = 16 warps).
// Warp tile = (TBM/MW) x (128/NW). Single barrier per K-stage, NSTG stages.
template<int TBM, int MW, int NW, int NSTG>
__global__ void __launch_bounds__(512, 1)
hmma_gemm(const __nv_bfloat16* __restrict__ Ah, const __nv_bfloat16* __restrict__ Al, int lda,
          const __nv_bfloat16* __restrict__ Bh, const __nv_bfloat16* __restrict__ Bl, int ldb,
          int K, const float* __restrict__ bias,
          float* __restrict__ C, int N, int ldc) {
    constexpr int MT = (TBM / MW) / 16;     // 16-row mma tiles per warp
    constexpr int NT = (128 / NW) / 8;      // 8-col mma tiles per warp
    constexpr int NP = NT / 2;              // 16-col ldsm groups per warp
    constexpr int T_AL = TBM * ROWB;
    constexpr int T_BH = 2 * TBM * ROWB;
    constexpr int T_BL = T_BH + BN * ROWB;
    constexpr int STAGE_B = 2 * (TBM + BN) * ROWB;
    constexpr int AREP = TBM / 128;         // A loader reps per half

    extern __shared__ char smem[];
    const uint32_t sb = smem_u32(smem);
    const int tid  = threadIdx.x;
    const int lane = tid & 31;
    const int wid  = tid >> 5;
    const int wm   = (wid % MW) * (TBM / MW);
    const int wn   = (wid / MW) * (128 / NW);
    const long m0  = (long)blockIdx.y * TBM;
    const long n0  = (long)blockIdx.x * BN;

    float acc[MT][NT][4];
#pragma unroll
    for (int i = 0; i < MT; i++)
#pragma unroll
        for (int j = 0; j < NT; j++)
#pragma unroll
            for (int c = 0; c < 4; c++) acc[i][j][c] = 0.f;

    uint32_t a_off[MT];
#pragma unroll
    for (int mt = 0; mt < MT; mt++)
        a_off[mt] = (uint32_t)(wm + mt * 16 + (lane & 15)) * ROWB + (lane >> 4) * 16;
    uint32_t b_off[NP];
#pragma unroll
    for (int np = 0; np < NP; np++)
        b_off[np] = T_BH
                  + (uint32_t)(wn + np * 16 + ((lane & 7) | ((lane >> 4) << 3))) * ROWB
                  + ((lane >> 3) & 1) * 16;

    const int arow = tid >> 2, aks = tid & 3;
    const uint32_t asw = (uint32_t)arow * ROWB + aks * 16;

    auto load_stage = [&](int buf, long kel) {
        uint32_t st = sb + buf * STAGE_B;
#pragma unroll
        for (int r = 0; r < AREP; r++) {
            long row = m0 + arow + r * 128;
            uint32_t d = st + asw + (uint32_t)(r * 128 * ROWB);
            cp16(d + 0,    Ah + row * lda + kel + aks * 8);
            cp16(d + T_AL, Al + row * lda + kel + aks * 8);
        }
        cp16(st + asw + T_BH, Bh + (n0 + arow) * ldb + kel + aks * 8);
        cp16(st + asw + T_BL, Bl + (n0 + arow) * ldb + kel + aks * 8);
    };

    const int S = K / BK;
#pragma unroll 1
    for (int p = 0; p < NSTG - 1; p++) {
        load_stage(p, (long)p * BK);
        cp_commit();
    }

#pragma unroll 1
    for (int s = 0; s < S; s++) {
        cp_wait<NSTG - 2>();
        __syncthreads();
        if (s + NSTG - 1 < S)
            load_stage((s + NSTG - 1) % NSTG, (long)(s + NSTG - 1) * BK);
        cp_commit();

        uint32_t st = sb + (s % NSTG) * STAGE_B;
#pragma unroll
        for (int kk = 0; kk < 2; kk++) {
            uint32_t ah[MT][4], al[MT][4];
#pragma unroll
            for (int mt = 0; mt < MT; mt++) {
                ldsm4(ah[mt], st + a_off[mt] + kk * 32);
                ldsm4(al[mt], st + T_AL + a_off[mt] + kk * 32);
            }
#pragma unroll
            for (int np = 0; np < NP; np++) {
                uint32_t bh[4], bl[4];
                ldsm4(bh, st + b_off[np] + kk * 32);
                ldsm4(bl, st + (T_BL - T_BH) + b_off[np] + kk * 32);
#pragma unroll
                for (int j = 0; j < 2; j++) {
                    int nt = np * 2 + j;
#pragma unroll
                    for (int mt = 0; mt < MT; mt++) {
                        mma16816(acc[mt][nt], ah[mt], bh[2 * j], bh[2 * j + 1]);
                        mma16816(acc[mt][nt], ah[mt], bl[2 * j], bl[2 * j + 1]);
                        mma16816(acc[mt][nt], al[mt], bh[2 * j], bh[2 * j + 1]);
                    }
                }
            }
        }
    }

    // epilogue
    const int gr = lane >> 2;
    const int gc = (lane & 3) * 2;
#pragma unroll
    for (int mt = 0; mt < MT; mt++) {
#pragma unroll
        for (int nt = 0; nt < NT; nt++) {
            int n = (int)n0 + wn + nt * 8 + gc;
            if (n < N) {
                long m = m0 + wm + mt * 16 + gr;
                float b0 = bias ? bias[n] : 0.f;
                float b1 = bias ? bias[n + 1] : 0.f;
                float2 v0 = make_float2(acc[mt][nt][0] + b0, acc[mt][nt][1] + b1);
                float2 v1 = make_float2(acc[mt][nt][2] + b0, acc[mt][nt][3] + b1);
                *reinterpret_cast<float2*>(C + m * ldc + n) = v0;
                *reinterpret_cast<float2*>(C + (m + 8) * ldc + n) = v1;
            }
        }
    }
}

// ---------------------------------------------------------------- attention
__global__ void attn_kernel(const float* __restrict__ boxes,
                            const float* __restrict__ pos_emb) {
    int row  = blockIdx.x * 8 + (threadIdx.x >> 5);
    int lane = threadIdx.x & 31;
    if (row >= NROWS) return;

    const float* region = g_region + (long)row * N1;
    float reg[7];
#pragma unroll
    for (int i = 0; i < 7; i++) {
        int e = lane + 32 * i;
        reg[i] = (e < PEMB) ? region[e] : 0.f;
    }

    const float* brow = boxes + (long)row * (2 * BOXL);
    int   idx[BOXL];
    float w[BOXL], sc[BOXL];
#pragma unroll
    for (int k = 0; k < BOXL; k++) {
        idx[k] = (int)brow[k];
        w[k]   = brow[BOXL + k];
    }

#pragma unroll
    for (int k = 0; k < BOXL; k++) {
        const float* pe = pos_emb + (long)idx[k] * PEMB;
        float p = 0.f;
#pragma unroll
        for (int i = 0; i < 7; i++) {
            int e = lane + 32 * i;
            if (e < PEMB) p += reg[i] * pe[e];
        }
#pragma unroll
        for (int o = 16; o > 0; o >>= 1)
            p += __shfl_xor_sync(0xffffffffu, p, o);
        sc[k] = tanhf(p);
    }

    float mx = -1e30f;
#pragma unroll
    for (int k = 0; k < BOXL; k++) mx = fmaxf(mx, sc[k]);
    float ssum = 0.f;
#pragma unroll
    for (int k = 0; k < BOXL; k++) { sc[k] = expf(sc[k] - mx); ssum += sc[k]; }
    float tot = 0.f;
#pragma unroll
    for (int k = 0; k < BOXL; k++) { sc[k] = sc[k] / ssum * w[k]; tot += sc[k]; }
    float inv = 1.f / (tot + 1e-6f);

#pragma unroll
    for (int i = 0; i < 7; i++) {
        int e = lane + 32 * i;
        if (e < PEMB) {
            float f = 0.f;
#pragma unroll
            for (int k = 0; k < BOXL; k++)
                f += sc[k] * pos_emb[(long)idx[k] * PEMB + e];
            f *= inv;
            __nv_bfloat16 h, l; split2(f, h, l);
            g_Xh[(long)row * K2 + K1 + e] = h;
            g_Xl[(long)row * K2 + K1 + e] = l;
        }
    }
}

// ---------------------------------------------------------------- L2 norm
__global__ void norm_kernel(float* __restrict__ out) {
    int row  = blockIdx.x * 8 + (threadIdx.x >> 5);
    int lane = threadIdx.x & 31;
    if (row >= NROWS) return;

    float4* p = reinterpret_cast<float4*>(out + (long)row * N2);
    float4 v[8];
    float s = 0.f;
#pragma unroll
    for (int i = 0; i < 8; i++) {
        v[i] = p[lane + 32 * i];
        s += v[i].x * v[i].x + v[i].y * v[i].y + v[i].z * v[i].z + v[i].w * v[i].w;
    }
#pragma unroll
    for (int o = 16; o > 0; o >>= 1)
        s += __shfl_xor_sync(0xffffffffu, s, o);
    float scale = 1.f / (sqrtf(s) + 1e-8f);
#pragma unroll
    for (int i = 0; i < 8; i++) {
        v[i].x *= scale; v[i].y *= scale; v[i].z *= scale; v[i].w *= scale;
        p[lane + 32 * i] = v[i];
    }
}

// ---------------------------------------------------------------- launch
#define SMEM1 (4 * 2 * (128 + 128) * ROWB)   // 163840 (TBM=128, 4 stages)
#define SMEM2 (3 * 2 * (256 + 128) * ROWB)   // 184320 (TBM=256, 3 stages)

extern "C" void kernel_launch(void* const* d_in, const int* in_sizes, int n_in,
                              void* d_out, int out_size) {
    const float* images  = (const float*)d_in[0];
    const float* tag     = (const float*)d_in[1];
    const float* boxes   = (const float*)d_in[2];
    const float* pos_emb = (const float*)d_in[3];
    const float* attn_W  = (const float*)d_in[4];
    const float* fc_W    = (const float*)d_in[5];
    const float* fc_b    = (const float*)d_in[6];
    float* out = (float*)d_out;

    cudaFuncSetAttribute(hmma_gemm<128, 4, 4, 4>,
                         cudaFuncAttributeMaxDynamicSharedMemorySize, SMEM1);
    cudaFuncSetAttribute(hmma_gemm<256, 8, 2, 3>,
                         cudaFuncAttributeMaxDynamicSharedMemorySize, SMEM2);

    void *xh, *xl, *w2h, *w2l, *w1h, *w1l, *rg;
    cudaGetSymbolAddress(&xh, g_Xh);   cudaGetSymbolAddress(&xl, g_Xl);
    cudaGetSymbolAddress(&w2h, g_W2h); cudaGetSymbolAddress(&w2l, g_W2l);
    cudaGetSymbolAddress(&w1h, g_W1h); cudaGetSymbolAddress(&w1l, g_W1l);
    cudaGetSymbolAddress(&rg, g_region);

    // 1. conversions
    convX_kernel<<<(NROWS * 768 + 255) / 256, 256>>>(images, tag);
    convW2_kernel<<<(N2 * K2 + 255) / 256, 256>>>(fc_W);
    convW1_kernel<<<(N1P * K1 + 255) / 256, 256>>>(attn_W);

    // 2. GEMM1: region = X[:, :2816] @ attn_W^T  (BM=128 -> 144 CTAs, 1 wave)
    {
        dim3 grid(N1P / BN, NROWS / 128);
        hmma_gemm<128, 4, 4, 4><<<grid, 512, SMEM1>>>(
            (const __nv_bfloat16*)xh, (const __nv_bfloat16*)xl, K2,
            (const __nv_bfloat16*)w1h, (const __nv_bfloat16*)w1l, K1,
            K1, nullptr, (float*)rg, N1, N1);
    }

    // 3. attention -> box_feat (bf16 split) into X[:, 2816:3016]
    attn_kernel<<<NROWS / 8, 256>>>(boxes, pos_emb);

    // 4. GEMM2: out = X @ W2^T + fc_b
    {
        dim3 grid(N2 / BN, NROWS / 256);
        hmma_gemm<256, 8, 2, 3><<<grid, 512, SMEM2>>>(
            (const __nv_bfloat16*)xh, (const __nv_bfloat16*)xl, K2,
            (const __nv_bfloat16*)w2h, (const __nv_bfloat16*)w2l, K2,
            K2, fc_b, out, N2, N2);
    }

    // 5. L2 normalize
    norm_kernel<<<NROWS / 8, 256>>>(out);
}